// round 4
// baseline (speedup 1.0000x reference)
#include <cuda_runtime.h>
#include <cuda_bf16.h>

#define NUM_TYPES 8
#define DIM_Q 64
#define NUM_NEURONS 64
#define NB 148            // blocks for bucketing kernels

typedef unsigned long long ull;

static constexpr int W0_ELEMS = NUM_TYPES * DIM_Q * NUM_NEURONS;   // 32768
static constexpr int B0_ELEMS = NUM_TYPES * NUM_NEURONS;           // 512
static constexpr int SMEM_FLOATS = W0_ELEMS + B0_ELEMS + B0_ELEMS; // 33792
static constexpr int SMEM_BYTES = SMEM_FLOATS * 4;                 // 135168

// scratch (static __device__ arrays are allowed; no allocation)
__device__ int g_counts[NB * NUM_TYPES];
__device__ int g_start [NB * NUM_TYPES];
__device__ int g_idx   [65536];

// ---------------- init: out = N * b1 (also un-poisons d_out) ----------------
__global__ void tnep_init_kernel(float* __restrict__ out,
                                 const float* __restrict__ b1, int n) {
    out[0] = b1[0] * (float)n;
}

// ---------------- bucketing: count / scan / scatter ----------------
__global__ void k_count(const int* __restrict__ Z, int n) {
    __shared__ int h[NUM_TYPES];
    if (threadIdx.x < NUM_TYPES) h[threadIdx.x] = 0;
    __syncthreads();
    const int per = (n + gridDim.x - 1) / gridDim.x;
    const int s = blockIdx.x * per;
    const int e = min(n, s + per);
    for (int i = s + threadIdx.x; i < e; i += blockDim.x)
        atomicAdd(&h[Z[i]], 1);
    __syncthreads();
    if (threadIdx.x < NUM_TYPES)
        g_counts[blockIdx.x * NUM_TYPES + threadIdx.x] = h[threadIdx.x];
}

__global__ void k_scan() {
    __shared__ int tot[NUM_TYPES];
    const int t = threadIdx.x;           // 8 threads, one per type
    int s = 0;
    for (int b = 0; b < NB; ++b) s += g_counts[b * NUM_TYPES + t];
    tot[t] = s;
    __syncthreads();
    int base = 0;
    for (int u = 0; u < t; ++u) base += tot[u];
    for (int b = 0; b < NB; ++b) {
        g_start[b * NUM_TYPES + t] = base;
        base += g_counts[b * NUM_TYPES + t];
    }
}

__global__ void k_scatter(const int* __restrict__ Z, int n) {
    __shared__ int off[NUM_TYPES];
    if (threadIdx.x < NUM_TYPES)
        off[threadIdx.x] = g_start[blockIdx.x * NUM_TYPES + threadIdx.x];
    __syncthreads();
    const int per = (n + gridDim.x - 1) / gridDim.x;
    const int s = blockIdx.x * per;
    const int e = min(n, s + per);
    for (int i = s + threadIdx.x; i < e; i += blockDim.x) {
        const int p = atomicAdd(&off[Z[i]], 1);
        g_idx[p] = i;
    }
}

// ---------------- main MLP kernel ----------------
__device__ __forceinline__ float fast_tanh(float x) {
    float r;
    asm("tanh.approx.f32 %0, %1;" : "=f"(r) : "f"(x));
    return r;
}

__global__ __launch_bounds__(512, 1)
void tnep_mlp(const float* __restrict__ q,
              const float* __restrict__ W0,
              const float* __restrict__ b0,
              const float* __restrict__ W1,
              const int*   __restrict__ Z,
              float* __restrict__ out,
              int n)
{
    extern __shared__ float smem[];
    float* sW0 = smem;                  // [t][d][k]
    float* sB0 = smem + W0_ELEMS;       // [t][k]
    float* sW1 = sB0 + B0_ELEMS;        // [t][k]

    for (int i = threadIdx.x; i < W0_ELEMS; i += blockDim.x) sW0[i] = W0[i];
    for (int i = threadIdx.x; i < B0_ELEMS; i += blockDim.x) sB0[i] = b0[i];
    for (int i = threadIdx.x; i < B0_ELEMS; i += blockDim.x) sW1[i] = W1[i];
    __syncthreads();

    const int lane   = threadIdx.x & 31;
    const int gwarp  = (blockIdx.x * blockDim.x + threadIdx.x) >> 5;
    const int nwarps = (gridDim.x * blockDim.x) >> 5;
    const int ntiles = (n + 31) >> 5;

    float esum = 0.0f;

    for (int tile = gwarp; tile < ntiles; tile += nwarps) {
        const int  ai    = tile * 32 + lane;
        const bool valid = (ai < n);
        const int  idx   = valid ? g_idx[ai] : g_idx[0];
        const int  z     = Z[idx];                      // warp-uniform (sorted)
        const float4* qrow = (const float4*)(q + (size_t)idx * DIM_Q);
        const float*  wz   = sW0 + z * (DIM_Q * NUM_NEURONS);

        float atomE = 0.0f;

        #pragma unroll
        for (int half = 0; half < 2; ++half) {          // 32 neurons per half
            ull acc[16];                                // 16 f32x2 pairs
            const ull* bp = (const ull*)(sB0 + z * NUM_NEURONS + half * 32);
            #pragma unroll
            for (int j = 0; j < 16; ++j) acc[j] = bp[j];

            #pragma unroll
            for (int dc = 0; dc < 2; ++dc) {            // d in chunks of 32
                float4 qv[8];
                #pragma unroll
                for (int j = 0; j < 8; ++j) qv[j] = qrow[dc * 8 + j];

                #pragma unroll
                for (int d = 0; d < 32; ++d) {
                    const float qd = ((const float*)qv)[d];
                    ull q2;
                    asm("mov.b64 %0, {%1, %1};" : "=l"(q2) : "f"(qd));
                    const ulonglong2* wp = (const ulonglong2*)
                        (wz + (dc * 32 + d) * NUM_NEURONS + half * 32);
                    #pragma unroll
                    for (int j = 0; j < 8; ++j) {       // 8 x LDS.128 broadcast
                        const ulonglong2 wv = wp[j];
                        asm("fma.rn.f32x2 %0, %1, %2, %0;"
                            : "+l"(acc[2 * j])     : "l"(wv.x), "l"(q2));
                        asm("fma.rn.f32x2 %0, %1, %2, %0;"
                            : "+l"(acc[2 * j + 1]) : "l"(wv.y), "l"(q2));
                    }
                }
            }

            // epilogue: tanh + dot with W1
            const ull* w1p = (const ull*)(sW1 + z * NUM_NEURONS + half * 32);
            #pragma unroll
            for (int j = 0; j < 16; ++j) {
                float a0, a1, w0f, w1f;
                asm("mov.b64 {%0, %1}, %2;" : "=f"(a0), "=f"(a1) : "l"(acc[j]));
                const ull wpair = w1p[j];
                asm("mov.b64 {%0, %1}, %2;" : "=f"(w0f), "=f"(w1f) : "l"(wpair));
                atomE = fmaf(fast_tanh(a0), w0f,
                        fmaf(fast_tanh(a1), w1f, atomE));
            }
        }

        if (valid) esum += atomE;
    }

    // warp reduce + one atomic per warp
    #pragma unroll
    for (int o = 16; o > 0; o >>= 1)
        esum += __shfl_xor_sync(0xffffffffu, esum, o);
    if (lane == 0)
        atomicAdd(out, esum);
}

extern "C" void kernel_launch(void* const* d_in, const int* in_sizes, int n_in,
                              void* d_out, int out_size) {
    // metadata order: descriptors, W0, b0, W1, b1, Z
    const float* q  = (const float*)d_in[0];
    const float* W0 = (const float*)d_in[1];
    const float* b0 = (const float*)d_in[2];
    const float* W1 = (const float*)d_in[3];
    const float* b1 = (const float*)d_in[4];
    const int*   Z  = (const int*)  d_in[5];
    float* out = (float*)d_out;

    const int n = in_sizes[5];   // N_ATOMS

    static bool attr_done = false;
    if (!attr_done) {
        cudaFuncSetAttribute(tnep_mlp,
                             cudaFuncAttributeMaxDynamicSharedMemorySize,
                             SMEM_BYTES);
        attr_done = true;
    }

    tnep_init_kernel<<<1, 1>>>(out, b1, n);
    k_count  <<<NB, 256>>>(Z, n);
    k_scan   <<<1, NUM_TYPES>>>();
    k_scatter<<<NB, 256>>>(Z, n);
    tnep_mlp <<<NB, 512, SMEM_BYTES>>>(q, W0, b0, W1, Z, out, n);
}

// round 7
// speedup vs baseline: 1.4676x; 1.4676x over previous
#include <cuda_runtime.h>
#include <cuda_bf16.h>

#define NUM_TYPES 8
#define DIM_Q 64
#define NN 64
#define NBLK 148
#define NTHR 384
#define NWARP 12
#define CHUNK_D 16
#define QPAD 34   // bank = (2*d + lane) % 32 -> conflict-free LDS/STS

typedef unsigned long long ull;

static constexpr int W0_ELEMS = NUM_TYPES * DIM_Q * NN;   // 32768
static constexpr int B_ELEMS  = NUM_TYPES * NN;           // 512
static constexpr int QSTAGE_F = NWARP * CHUNK_D * QPAD;   // 6528
static constexpr int IDX_CAP  = 768;                      // >= ceil(n/NBLK)
// floats: W0 + b0 + W1 + qstage; ints: idx + hist/base/off
static constexpr int SMEM_BYTES =
    (W0_ELEMS + B_ELEMS + B_ELEMS + QSTAGE_F) * 4 + (IDX_CAP + 24) * 4;

// ---------------- init: out = N * b1 (un-poisons d_out) ----------------
__global__ void tnep_init_kernel(float* __restrict__ out,
                                 const float* __restrict__ b1, int n) {
    out[0] = b1[0] * (float)n;
}

__device__ __forceinline__ float fast_tanh(float x) {
    float r;
    asm("tanh.approx.f32 %0, %1;" : "=f"(r) : "f"(x));
    return r;
}

__global__ __launch_bounds__(NTHR, 1)
void tnep_fused(const float* __restrict__ q,
                const float* __restrict__ W0,
                const float* __restrict__ b0,
                const float* __restrict__ W1,
                const int*   __restrict__ Z,
                float* __restrict__ out,
                int n, int per)
{
    extern __shared__ float sm[];
    float* sW0 = sm;                       // [t][d][k]
    float* sB0 = sm + W0_ELEMS;
    float* sW1 = sB0 + B_ELEMS;
    float* sQT = sW1 + B_ELEMS;            // per-warp [CHUNK_D][QPAD]
    int*   sIdx = (int*)(sQT + QSTAGE_F);  // packed (z<<24)|atom_idx
    int*   hist = sIdx + IDX_CAP;
    int*   basep = hist + NUM_TYPES;
    int*   off  = basep + NUM_TYPES;

    const int tid = threadIdx.x;

    // ---- weight preload (vectorized; W0 is L2-resident across 148 blocks) ----
    for (int i = tid; i < W0_ELEMS / 4; i += NTHR)
        ((float4*)sW0)[i] = ((const float4*)W0)[i];
    for (int i = tid; i < B_ELEMS / 4; i += NTHR)
        ((float4*)sB0)[i] = ((const float4*)b0)[i];
    for (int i = tid; i < B_ELEMS / 4; i += NTHR)
        ((float4*)sW1)[i] = ((const float4*)W1)[i];
    if (tid < NUM_TYPES) hist[tid] = 0;
    __syncthreads();

    // ---- local counting sort of this block's chunk ----
    const int s   = blockIdx.x * per;
    const int cnt = max(0, min(n - s, per));
    const int cnt_pad = (cnt + 31) & ~31;

    for (int i = tid; i < cnt_pad; i += NTHR) {          // histogram (warp-aggregated)
        const bool v = (i < cnt);
        const int  z = v ? Z[s + i] : -1;
        const unsigned m = __match_any_sync(0xffffffffu, z);
        if (v && ((m & (m - 1)) == 0 || (threadIdx.x & 31) == (__ffs(m) - 1)))
            atomicAdd(&hist[z], __popc(m));
    }
    __syncthreads();
    if (tid == 0) {
        int acc = 0;
        #pragma unroll
        for (int t = 0; t < NUM_TYPES; ++t) { basep[t] = acc; off[t] = acc; acc += hist[t]; }
    }
    __syncthreads();
    for (int i = tid; i < cnt_pad; i += NTHR) {          // scatter (warp-aggregated)
        const bool v = (i < cnt);
        const int  z = v ? Z[s + i] : -1;
        const unsigned m = __match_any_sync(0xffffffffu, z);
        const int lane31 = threadIdx.x & 31;
        const int leader = __ffs(m) - 1;
        const int rank   = __popc(m & ((1u << lane31) - 1));
        int p0 = 0;
        if (v && lane31 == leader) p0 = atomicAdd(&off[z], __popc(m));
        p0 = __shfl_sync(0xffffffffu, p0, leader);
        if (v) sIdx[p0 + rank] = (z << 24) | (s + i);
    }
    __syncthreads();

    // ---- MLP: one atom per lane, 32-atom tiles, mostly z-uniform ----
    const int wid  = tid >> 5;
    const int lane = tid & 31;
    float* myQ = sQT + wid * (CHUNK_D * QPAD);
    const int ntiles = (cnt + 31) >> 5;

    float esum = 0.0f;

    for (int t = wid; t < ntiles; t += NWARP) {
        const int  li    = t * 32 + lane;
        const bool valid = (li < cnt);
        const int  packed = sIdx[valid ? li : 0];
        const int  idx = packed & 0xFFFFFF;
        const int  z   = packed >> 24;
        const float* wz = sW0 + z * (DIM_Q * NN);

        // accumulators: 64 neurons as 32 f32x2, seeded with bias
        ull acc[32];
        {
            const ulonglong2* bp = (const ulonglong2*)(sB0 + z * NN);
            #pragma unroll
            for (int j = 0; j < 16; ++j) {
                const ulonglong2 v = bp[j];
                acc[2 * j] = v.x; acc[2 * j + 1] = v.y;
            }
        }

        #pragma unroll
        for (int c = 0; c < 4; ++c) {
            // stage q chunk transposed: 32 rows x 16 d, coalesced 64B/row reads
            #pragma unroll
            for (int i = 0; i < 16; ++i) {
                const int row  = 2 * i + (lane >> 4);
                const int dloc = lane & 15;
                const int ridx = __shfl_sync(0xffffffffu, idx, row);
                const float v = __ldg(q + (size_t)ridx * DIM_Q + c * CHUNK_D + dloc);
                myQ[dloc * QPAD + row] = v;   // conflict-free (stride 34)
            }
            __syncwarp();

            #pragma unroll
            for (int d = 0; d < CHUNK_D; ++d) {
                const float qd = myQ[d * QPAD + lane];   // own atom's q[d], 1 wf
                ull q2;
                asm("mov.b64 %0, {%1, %1};" : "=l"(q2) : "f"(qd));
                const ulonglong2* wp =
                    (const ulonglong2*)(wz + (c * CHUNK_D + d) * NN);
                #pragma unroll
                for (int j = 0; j < 16; ++j) {           // broadcast LDS.128
                    const ulonglong2 wv = wp[j];
                    asm("fma.rn.f32x2 %0, %1, %2, %0;"
                        : "+l"(acc[2 * j])     : "l"(wv.x), "l"(q2));
                    asm("fma.rn.f32x2 %0, %1, %2, %0;"
                        : "+l"(acc[2 * j + 1]) : "l"(wv.y), "l"(q2));
                }
            }
            __syncwarp();
        }

        // epilogue: tanh + dot with W1[z]
        float atomE = 0.0f;
        const ull* w1p = (const ull*)(sW1 + z * NN);
        #pragma unroll
        for (int j = 0; j < 32; ++j) {
            float a0, a1, u0, u1;
            asm("mov.b64 {%0, %1}, %2;" : "=f"(a0), "=f"(a1) : "l"(acc[j]));
            const ull wpair = w1p[j];
            asm("mov.b64 {%0, %1}, %2;" : "=f"(u0), "=f"(u1) : "l"(wpair));
            atomE = fmaf(fast_tanh(a0), u0, fmaf(fast_tanh(a1), u1, atomE));
        }
        if (valid) esum += atomE;
    }

    // warp reduce + one atomic per warp
    #pragma unroll
    for (int o = 16; o > 0; o >>= 1)
        esum += __shfl_xor_sync(0xffffffffu, esum, o);
    if (lane == 0 && esum != 0.0f)
        atomicAdd(out, esum);
}

extern "C" void kernel_launch(void* const* d_in, const int* in_sizes, int n_in,
                              void* d_out, int out_size) {
    // metadata order: descriptors, W0, b0, W1, b1, Z
    const float* q  = (const float*)d_in[0];
    const float* W0 = (const float*)d_in[1];
    const float* b0 = (const float*)d_in[2];
    const float* W1 = (const float*)d_in[3];
    const float* b1 = (const float*)d_in[4];
    const int*   Z  = (const int*)  d_in[5];
    float* out = (float*)d_out;

    const int n = in_sizes[5];            // N_ATOMS
    int per = (n + NBLK - 1) / NBLK;      // chunk per block
    if (per > IDX_CAP) per = IDX_CAP;     // safety (n <= 113k)

    cudaFuncSetAttribute(tnep_fused,
                         cudaFuncAttributeMaxDynamicSharedMemorySize,
                         SMEM_BYTES);

    tnep_init_kernel<<<1, 1>>>(out, b1, n);
    tnep_fused<<<NBLK, NTHR, SMEM_BYTES>>>(q, W0, b0, W1, Z, out, n, per);
}

// round 9
// speedup vs baseline: 2.3198x; 1.5807x over previous
#include <cuda_runtime.h>
#include <cstdint>

#define NUM_TYPES 8
#define NBLK 148
#define NTHR 256
#define IDX_CAP 1024
#define MAX_TILES 40
#define WSTRIDE 72     // weight row stride (floats): bank = 8*k + n -> conflict-free B frags

// ---- dynamic smem byte offsets ----
#define SW_OFF   0          // 8 types * 64 * 72 * 4 = 147456 B (tf32-converted W0, [t][d][n])
#define B0_OFF   147456     // 2048
#define W1_OFF   149504     // 2048
#define IDX_OFF  151552     // 1056 ints = 4224 B (sorted atom indices + pad)
#define HIST_OFF 155776
#define BASE_OFF 155808
#define OFF_OFF  155840
#define TZ_OFF   155872     // MAX_TILES ints
#define TS_OFF   156032
#define TL_OFF   156192
#define NT_OFF   156352
#define SMEM_BYTES 156416

__device__ __forceinline__ uint32_t f2tf(float x) {
    uint32_t r; asm("cvt.rna.tf32.f32 %0, %1;" : "=r"(r) : "f"(x)); return r;
}
__device__ __forceinline__ float fast_tanh(float x) {
    float r; asm("tanh.approx.f32 %0, %1;" : "=f"(r) : "f"(x)); return r;
}
__device__ __forceinline__ void mma8(float* c, const uint32_t* a,
                                     uint32_t b0, uint32_t b1) {
    asm volatile("mma.sync.aligned.m16n8k8.row.col.f32.tf32.tf32.f32 "
        "{%0,%1,%2,%3}, {%4,%5,%6,%7}, {%8,%9}, {%0,%1,%2,%3};"
        : "+f"(c[0]), "+f"(c[1]), "+f"(c[2]), "+f"(c[3])
        : "r"(a[0]), "r"(a[1]), "r"(a[2]), "r"(a[3]), "r"(b0), "r"(b1));
}

// ---------------- init: out = N * b1 (un-poisons d_out) ----------------
__global__ void tnep_init_kernel(float* __restrict__ out,
                                 const float* __restrict__ b1, int n) {
    out[0] = b1[0] * (float)n;
}

__global__ __launch_bounds__(NTHR, 1)
void tnep_mma(const float* __restrict__ q,
              const float* __restrict__ W0,
              const float* __restrict__ b0,
              const float* __restrict__ W1,
              const int*   __restrict__ Z,
              float* __restrict__ out,
              int n, int per)
{
    extern __shared__ char smc[];
    float* sW  = (float*)(smc + SW_OFF);
    float* sB0 = (float*)(smc + B0_OFF);
    float* sW1 = (float*)(smc + W1_OFF);
    int*   sIdx = (int*)(smc + IDX_OFF);
    int*   hist = (int*)(smc + HIST_OFF);
    int*   bse  = (int*)(smc + BASE_OFF);
    int*   off  = (int*)(smc + OFF_OFF);
    int*   tZ   = (int*)(smc + TZ_OFF);
    int*   tS   = (int*)(smc + TS_OFF);
    int*   tL   = (int*)(smc + TL_OFF);
    int*   nT   = (int*)(smc + NT_OFF);

    const int tid  = threadIdx.x;
    const int wid  = tid >> 5;
    const int lane = tid & 31;

    // ---- stage W0 -> tf32, [t][d][WSTRIDE] layout; biases; prefill sIdx ----
    for (int i = tid; i < 8192; i += NTHR) {            // 8192 float4
        const int t = i >> 10, j = i & 1023;
        const int d = j >> 4, c4 = j & 15;
        const float4 v = ((const float4*)W0)[i];
        uint4 u;
        u.x = f2tf(v.x); u.y = f2tf(v.y); u.z = f2tf(v.z); u.w = f2tf(v.w);
        *(uint4*)(sW + (t * 64 + d) * WSTRIDE + c4 * 4) = u;
    }
    for (int i = tid; i < NUM_TYPES * 64; i += NTHR) {
        sB0[i] = b0[i];
        sW1[i] = W1[i];
    }
    for (int i = tid; i < IDX_CAP + 32; i += NTHR) sIdx[i] = 0;
    if (tid < NUM_TYPES) hist[tid] = 0;
    __syncthreads();

    // ---- local counting sort by type ----
    const int s   = blockIdx.x * per;
    const int cnt = max(0, min(n - s, per));
    const int cnt_pad = (cnt + 31) & ~31;

    for (int i = tid; i < cnt_pad; i += NTHR) {
        const bool v = (i < cnt);
        const int  z = v ? Z[s + i] : -1;
        const unsigned m = __match_any_sync(0xffffffffu, z);
        if (v && (lane == (__ffs(m) - 1)))
            atomicAdd(&hist[z], __popc(m));
    }
    __syncthreads();
    if (tid == 0) {
        int acc = 0, nt = 0;
        #pragma unroll
        for (int t = 0; t < NUM_TYPES; ++t) { bse[t] = acc; off[t] = acc; acc += hist[t]; }
        for (int t = 0; t < NUM_TYPES; ++t) {
            int c = hist[t], st = bse[t];
            while (c > 0 && nt < MAX_TILES) {
                tZ[nt] = t; tS[nt] = st; tL[nt] = min(32, c);
                st += 32; c -= 32; ++nt;
            }
        }
        nT[0] = nt;
    }
    __syncthreads();
    for (int i = tid; i < cnt_pad; i += NTHR) {
        const bool v = (i < cnt);
        const int  z = v ? Z[s + i] : -1;
        const unsigned m = __match_any_sync(0xffffffffu, z);
        const int leader = __ffs(m) - 1;
        const int rank   = __popc(m & ((1u << lane) - 1));
        int p0 = 0;
        if (v && lane == leader) p0 = atomicAdd(&off[z], __popc(m));
        p0 = __shfl_sync(0xffffffffu, p0, leader);
        if (v) sIdx[p0 + rank] = s + i;
    }
    __syncthreads();

    // ---- MMA mainloop: one warp per 32-atom type-pure tile ----
    const int ntiles = nT[0];
    const int g  = lane >> 2;       // 0..7 : A row group / B col
    const int t4 = lane & 3;        // 0..3 : A col / B row
    float esum = 0.0f;

    for (int ti = wid; ti < ntiles; ti += NTHR / 32) {
        const int z   = tZ[ti];
        const int ts  = tS[ti];
        const int len = tL[ti];
        const bool hasM1 = (len > 16);

        const float* rp0 = q + (size_t)sIdx[ts + g]      * 64;
        const float* rp1 = q + (size_t)sIdx[ts + g + 8]  * 64;
        const float* rp2 = q + (size_t)sIdx[ts + g + 16] * 64;
        const float* rp3 = q + (size_t)sIdx[ts + g + 24] * 64;

        float C[8][8];                       // [ntile][m0 c0..c3 | m1 c0..c3]
        #pragma unroll
        for (int i = 0; i < 8; ++i)
            #pragma unroll
            for (int j = 0; j < 8; ++j) C[i][j] = 0.0f;

        const float* wz = sW + z * (64 * WSTRIDE);

        #pragma unroll
        for (int kc = 0; kc < 8; ++kc) {
            const int c0 = kc * 8 + t4, c4 = c0 + 4;

            // A fragments (rows g,g+8 | g+16,g+24), Markidis hi/lo split
            uint32_t ah[4], al[4], yh[4], yl[4];
            {
                const float x0 = __ldg(rp0 + c0), x1 = __ldg(rp1 + c0);
                const float x2 = __ldg(rp0 + c4), x3 = __ldg(rp1 + c4);
                ah[0] = f2tf(x0); al[0] = f2tf(x0 - __uint_as_float(ah[0]));
                ah[1] = f2tf(x1); al[1] = f2tf(x1 - __uint_as_float(ah[1]));
                ah[2] = f2tf(x2); al[2] = f2tf(x2 - __uint_as_float(ah[2]));
                ah[3] = f2tf(x3); al[3] = f2tf(x3 - __uint_as_float(ah[3]));
            }
            if (hasM1) {
                const float x0 = __ldg(rp2 + c0), x1 = __ldg(rp3 + c0);
                const float x2 = __ldg(rp2 + c4), x3 = __ldg(rp3 + c4);
                yh[0] = f2tf(x0); yl[0] = f2tf(x0 - __uint_as_float(yh[0]));
                yh[1] = f2tf(x1); yl[1] = f2tf(x1 - __uint_as_float(yh[1]));
                yh[2] = f2tf(x2); yl[2] = f2tf(x2 - __uint_as_float(yh[2]));
                yh[3] = f2tf(x3); yl[3] = f2tf(x3 - __uint_as_float(yh[3]));
            }

            // B fragments: b0 at (kc*8+t4, nt*8+g), b1 at +4 rows. bank=8k+n: conflict-free
            const float* wk = wz + (kc * 8 + t4) * WSTRIDE + g;
            #pragma unroll
            for (int nt = 0; nt < 8; ++nt) {
                const uint32_t b0f = __float_as_uint(wk[nt * 8]);
                const uint32_t b1f = __float_as_uint(wk[nt * 8 + 4 * WSTRIDE]);
                mma8(C[nt],     ah, b0f, b1f);
                mma8(C[nt],     al, b0f, b1f);
                if (hasM1) {
                    mma8(C[nt] + 4, yh, b0f, b1f);
                    mma8(C[nt] + 4, yl, b0f, b1f);
                }
            }
        }

        // epilogue: bias + tanh + dot W1, mask padded rows, accumulate scalar
        const float* zb = sB0 + z * 64;
        const float* zw = sW1 + z * 64;
        const bool v0 = (g      < len), v1 = (g + 8  < len);
        const bool v2 = (g + 16 < len), v3 = (g + 24 < len);
        #pragma unroll
        for (int nt = 0; nt < 8; ++nt) {
            const int n0 = nt * 8 + 2 * t4, n1 = n0 + 1;
            const float bb0 = zb[n0], bb1 = zb[n1];
            const float ww0 = zw[n0], ww1 = zw[n1];
            if (v0) esum += fast_tanh(C[nt][0] + bb0) * ww0
                          + fast_tanh(C[nt][1] + bb1) * ww1;
            if (v1) esum += fast_tanh(C[nt][2] + bb0) * ww0
                          + fast_tanh(C[nt][3] + bb1) * ww1;
            if (v2) esum += fast_tanh(C[nt][4] + bb0) * ww0
                          + fast_tanh(C[nt][5] + bb1) * ww1;
            if (v3) esum += fast_tanh(C[nt][6] + bb0) * ww0
                          + fast_tanh(C[nt][7] + bb1) * ww1;
        }
    }

    // ---- reduce + one atomic per warp ----
    #pragma unroll
    for (int o = 16; o > 0; o >>= 1)
        esum += __shfl_xor_sync(0xffffffffu, esum, o);
    if (lane == 0)
        atomicAdd(out, esum);
}

extern "C" void kernel_launch(void* const* d_in, const int* in_sizes, int n_in,
                              void* d_out, int out_size) {
    // metadata order: descriptors, W0, b0, W1, b1, Z
    const float* q  = (const float*)d_in[0];
    const float* W0 = (const float*)d_in[1];
    const float* b0 = (const float*)d_in[2];
    const float* W1 = (const float*)d_in[3];
    const float* b1 = (const float*)d_in[4];
    const int*   Z  = (const int*)  d_in[5];
    float* out = (float*)d_out;

    const int n = in_sizes[5];            // N_ATOMS
    int per = (n + NBLK - 1) / NBLK;
    if (per > IDX_CAP) per = IDX_CAP;

    cudaFuncSetAttribute(tnep_mma,
                         cudaFuncAttributeMaxDynamicSharedMemorySize,
                         SMEM_BYTES);

    tnep_init_kernel<<<1, 1>>>(out, b1, n);
    tnep_mma<<<NBLK, NTHR, SMEM_BYTES>>>(q, W0, b0, W1, Z, out, n, per);
}

// round 10
// speedup vs baseline: 2.5980x; 1.1199x over previous
#include <cuda_runtime.h>
#include <cstdint>

#define NUM_TYPES 8
#define NBLK 148
#define NTHR 512
#define NWARP 16
#define IDX_CAP 1024
#define MAX_TILES 32

// ---- dynamic smem byte offsets ----
#define SW_OFF   0          // 131072 B : W0 tf32, [t][k][n^ (8*(k&7))]  (no pad)
#define SQ_OFF   131072     // 65536 B  : per-warp 4KB half-tile A buffer
#define B0_OFF   196608     // 2048
#define W1_OFF   198656     // 2048
#define IDX_OFF  200704     // (1024+32)*4 = 4224
#define HIST_OFF 204928
#define BASE_OFF 204960
#define OFF_OFF  204992
#define TZ_OFF   205024
#define TS_OFF   205152
#define TL_OFF   205280
#define NT_OFF   205408
#define SMEM_BYTES 205568

__device__ __forceinline__ uint32_t f2tf(float x) {
    uint32_t r; asm("cvt.rna.tf32.f32 %0, %1;" : "=r"(r) : "f"(x)); return r;
}
__device__ __forceinline__ float fast_tanh(float x) {
    float r; asm("tanh.approx.f32 %0, %1;" : "=f"(r) : "f"(x)); return r;
}
__device__ __forceinline__ void mma8(float* c, const uint32_t* a,
                                     uint32_t b0, uint32_t b1) {
    asm volatile("mma.sync.aligned.m16n8k8.row.col.f32.tf32.tf32.f32 "
        "{%0,%1,%2,%3}, {%4,%5,%6,%7}, {%8,%9}, {%0,%1,%2,%3};"
        : "+f"(c[0]), "+f"(c[1]), "+f"(c[2]), "+f"(c[3])
        : "r"(a[0]), "r"(a[1]), "r"(a[2]), "r"(a[3]), "r"(b0), "r"(b1));
}

// ---------------- init: out = N * b1 (un-poisons d_out) ----------------
__global__ void tnep_init_kernel(float* __restrict__ out,
                                 const float* __restrict__ b1, int n) {
    out[0] = b1[0] * (float)n;
}

__global__ __launch_bounds__(NTHR, 1)
void tnep_mma(const float* __restrict__ q,
              const float* __restrict__ W0,
              const float* __restrict__ b0,
              const float* __restrict__ W1,
              const int*   __restrict__ Z,
              float* __restrict__ out,
              int n, int per)
{
    extern __shared__ char smc[];
    uint32_t* sW  = (uint32_t*)(smc + SW_OFF);   // tf32 weights, swizzled
    float* sB0 = (float*)(smc + B0_OFF);
    float* sW1 = (float*)(smc + W1_OFF);
    int* sIdx = (int*)(smc + IDX_OFF);
    int* hist = (int*)(smc + HIST_OFF);
    int* bse  = (int*)(smc + BASE_OFF);
    int* off  = (int*)(smc + OFF_OFF);
    int* tZ   = (int*)(smc + TZ_OFF);
    int* tS   = (int*)(smc + TS_OFF);
    int* tL   = (int*)(smc + TL_OFF);
    int* nT   = (int*)(smc + NT_OFF);

    const int tid  = threadIdx.x;
    const int wid  = tid >> 5;
    const int lane = tid & 31;

    // ---- stage W0 -> tf32, layout [t][k=d][n ^ 8*(d&7)] (XOR swizzle, no pad) ----
    for (int i = tid; i < 8192; i += NTHR) {            // 8192 float4
        const int t = i >> 10, j = i & 1023;
        const int d = j >> 4, n4 = j & 15;
        const float4 v = ((const float4*)W0)[i];
        uint4 u;
        u.x = f2tf(v.x); u.y = f2tf(v.y); u.z = f2tf(v.z); u.w = f2tf(v.w);
        const int dst = t * 4096 + d * 64 + 4 * (n4 ^ (2 * (d & 7)));
        *(uint4*)(sW + dst) = u;
    }
    for (int i = tid; i < NUM_TYPES * 64; i += NTHR) {
        sB0[i] = b0[i];
        sW1[i] = W1[i];
    }
    for (int i = tid; i < IDX_CAP + 32; i += NTHR) sIdx[i] = 0;
    if (tid < NUM_TYPES) hist[tid] = 0;
    __syncthreads();

    // ---- local counting sort by type ----
    const int s   = blockIdx.x * per;
    const int cnt = max(0, min(n - s, per));
    const int cnt_pad = (cnt + 31) & ~31;

    for (int i = tid; i < cnt_pad; i += NTHR) {
        const bool v = (i < cnt);
        const int  z = v ? Z[s + i] : -1;
        const unsigned m = __match_any_sync(0xffffffffu, z);
        if (v && (lane == (__ffs(m) - 1)))
            atomicAdd(&hist[z], __popc(m));
    }
    __syncthreads();
    if (tid == 0) {
        int acc = 0, nt = 0;
        #pragma unroll
        for (int t = 0; t < NUM_TYPES; ++t) { bse[t] = acc; off[t] = acc; acc += hist[t]; }
        for (int t = 0; t < NUM_TYPES; ++t) {
            int c = hist[t], st = bse[t];
            while (c > 0 && nt < MAX_TILES) {
                tZ[nt] = t; tS[nt] = st; tL[nt] = min(32, c);
                st += 32; c -= 32; ++nt;
            }
        }
        nT[0] = nt;
    }
    __syncthreads();
    for (int i = tid; i < cnt_pad; i += NTHR) {
        const bool v = (i < cnt);
        const int  z = v ? Z[s + i] : -1;
        const unsigned m = __match_any_sync(0xffffffffu, z);
        const int leader = __ffs(m) - 1;
        const int rank   = __popc(m & ((1u << lane) - 1));
        int p0 = 0;
        if (v && lane == leader) p0 = atomicAdd(&off[z], __popc(m));
        p0 = __shfl_sync(0xffffffffu, p0, leader);
        if (v) sIdx[p0 + rank] = s + i;
    }
    __syncthreads();

    // ---- MMA mainloop: one warp per 32-atom type-pure tile ----
    const int ntiles = nT[0];
    const int g  = lane >> 2;       // 0..7
    const int t4 = lane & 3;        // 0..3
    uint32_t* wq = (uint32_t*)(smc + SQ_OFF) + wid * 1024;  // 32 rows x 32 k (tf32)
    const int srow = lane >> 3;     // staging: 0..3
    const int sc4  = lane & 7;      // staging: col4 0..7
    float esum = 0.0f;

    for (int ti = wid; ti < ntiles; ti += NWARP) {
        const int z   = tZ[ti];
        const int ts  = tS[ti];
        const int len = tL[ti];

        float C[8][8];
        #pragma unroll
        for (int i = 0; i < 8; ++i)
            #pragma unroll
            for (int j = 0; j < 8; ++j) C[i][j] = 0.0f;

        const uint32_t* wz = sW + z * 4096;

        #pragma unroll
        for (int h = 0; h < 2; ++h) {            // k-halves: cols [32h, 32h+32)
            // stage half-tile A: coalesced LDG.128, tf32 cvt, XOR-swizzled STS.128
            #pragma unroll
            for (int it = 0; it < 8; ++it) {
                const int r = 4 * it + srow;
                const int row = sIdx[ts + r];
                const float4 v = *(const float4*)(q + (size_t)row * 64 + h * 32 + 4 * sc4);
                uint4 u;
                u.x = f2tf(v.x); u.y = f2tf(v.y); u.z = f2tf(v.z); u.w = f2tf(v.w);
                *(uint4*)(wq + r * 32 + 4 * (sc4 ^ (r & 7))) = u;
            }
            __syncwarp();

            #pragma unroll
            for (int kcl = 0; kcl < 4; ++kcl) {  // local k-chunk; global kc = 4h+kcl
                const int kc = 4 * h + kcl;
                const int kx = 4 * g;            // A-swizzle const (r&7 == g for all frag rows)

                // A fragments from smem (conflict-free LDS.32)
                uint32_t a0[4], a1[4];
                {
                    const int k0 = 8 * kcl + t4, k4 = k0 + 4;
                    a0[0] = wq[(g     ) * 32 + (k0 ^ kx)];
                    a0[1] = wq[(g +  8) * 32 + (k0 ^ kx)];
                    a0[2] = wq[(g     ) * 32 + (k4 ^ kx)];
                    a0[3] = wq[(g +  8) * 32 + (k4 ^ kx)];
                    a1[0] = wq[(g + 16) * 32 + (k0 ^ kx)];
                    a1[1] = wq[(g + 24) * 32 + (k0 ^ kx)];
                    a1[2] = wq[(g + 16) * 32 + (k4 ^ kx)];
                    a1[3] = wq[(g + 24) * 32 + (k4 ^ kx)];
                }

                // B fragments: (k=8kc+t4, n=8nt+g), swizzled n -> conflict-free
                const int kb0 = 8 * kc + t4, kb1 = kb0 + 4;
                const uint32_t* wr0 = wz + kb0 * 64;
                const uint32_t* wr1 = wz + kb1 * 64;
                const int sx0 = 8 * (kb0 & 7);   // = 8*t4
                const int sx1 = 8 * (kb1 & 7);   // = 8*(t4+4)
                #pragma unroll
                for (int nt = 0; nt < 8; ++nt) {
                    const int nn = 8 * nt + g;
                    const uint32_t bf0 = wr0[nn ^ sx0];
                    const uint32_t bf1 = wr1[nn ^ sx1];
                    mma8(C[nt],     a0, bf0, bf1);
                    mma8(C[nt] + 4, a1, bf0, bf1);
                }
            }
            __syncwarp();
        }

        // epilogue: bias + tanh + dot W1, mask padded rows
        const float* zb = sB0 + z * 64;
        const float* zw = sW1 + z * 64;
        const bool v0 = (g      < len), v1 = (g + 8  < len);
        const bool v2 = (g + 16 < len), v3 = (g + 24 < len);
        #pragma unroll
        for (int nt = 0; nt < 8; ++nt) {
            const int n0 = nt * 8 + 2 * t4, n1 = n0 + 1;
            const float bb0 = zb[n0], bb1 = zb[n1];
            const float ww0 = zw[n0], ww1 = zw[n1];
            if (v0) esum += fast_tanh(C[nt][0] + bb0) * ww0
                          + fast_tanh(C[nt][1] + bb1) * ww1;
            if (v1) esum += fast_tanh(C[nt][2] + bb0) * ww0
                          + fast_tanh(C[nt][3] + bb1) * ww1;
            if (v2) esum += fast_tanh(C[nt][4] + bb0) * ww0
                          + fast_tanh(C[nt][5] + bb1) * ww1;
            if (v3) esum += fast_tanh(C[nt][6] + bb0) * ww0
                          + fast_tanh(C[nt][7] + bb1) * ww1;
        }
    }

    // ---- reduce + one atomic per warp ----
    #pragma unroll
    for (int o = 16; o > 0; o >>= 1)
        esum += __shfl_xor_sync(0xffffffffu, esum, o);
    if (lane == 0)
        atomicAdd(out, esum);
}

extern "C" void kernel_launch(void* const* d_in, const int* in_sizes, int n_in,
                              void* d_out, int out_size) {
    // metadata order: descriptors, W0, b0, W1, b1, Z
    const float* q  = (const float*)d_in[0];
    const float* W0 = (const float*)d_in[1];
    const float* b0 = (const float*)d_in[2];
    const float* W1 = (const float*)d_in[3];
    const float* b1 = (const float*)d_in[4];
    const int*   Z  = (const int*)  d_in[5];
    float* out = (float*)d_out;

    const int n = in_sizes[5];            // N_ATOMS
    int per = (n + NBLK - 1) / NBLK;
    if (per > IDX_CAP) per = IDX_CAP;

    cudaFuncSetAttribute(tnep_mma,
                         cudaFuncAttributeMaxDynamicSharedMemorySize,
                         SMEM_BYTES);

    tnep_init_kernel<<<1, 1>>>(out, b1, n);
    tnep_mma<<<NBLK, NTHR, SMEM_BYTES>>>(q, W0, b0, W1, Z, out, n, per);
}

// round 11
// speedup vs baseline: 2.8748x; 1.1065x over previous
#include <cuda_runtime.h>
#include <cstdint>

#define NUM_TYPES 8
#define NBLK 148
#define NTHR 512
#define NWARP 16
#define IDX_CAP 1024
#define MAX_TILES 32

// ---- dynamic smem byte offsets ----
#define SW_OFF   0          // 131072 B : W0 fp32 raw, [t][k][n ^ 8*(k&7)]
#define SQ_OFF   131072     // 65536 B  : per-warp 4KB half-tile A buffer (fp32 raw)
#define B0_OFF   196608     // 2048
#define W1_OFF   198656     // 2048
#define IDX_OFF  200704     // (1024+32)*4 = 4224
#define HIST_OFF 204928
#define BASE_OFF 204960
#define OFF_OFF  204992
#define TZ_OFF   205024
#define TS_OFF   205152
#define TL_OFF   205280
#define NT_OFF   205408
#define SMEM_BYTES 205568

__device__ __forceinline__ uint32_t smem_u32(const void* p) {
    uint32_t a;
    asm("{ .reg .u64 t; cvta.to.shared.u64 t, %1; cvt.u32.u64 %0, t; }" : "=r"(a) : "l"(p));
    return a;
}
__device__ __forceinline__ uint32_t f2tf(float x) {
    uint32_t r; asm("cvt.rna.tf32.f32 %0, %1;" : "=r"(r) : "f"(x)); return r;
}
__device__ __forceinline__ float fast_tanh(float x) {
    float r; asm("tanh.approx.f32 %0, %1;" : "=f"(r) : "f"(x)); return r;
}
__device__ __forceinline__ void cpa16(uint32_t dst, const void* src) {
    asm volatile("cp.async.cg.shared.global [%0], [%1], 16;"
                 :: "r"(dst), "l"(src) : "memory");
}
__device__ __forceinline__ void cpa_commit() {
    asm volatile("cp.async.commit_group;" ::: "memory");
}
__device__ __forceinline__ void cpa_wait0() {
    asm volatile("cp.async.wait_group 0;" ::: "memory");
}
__device__ __forceinline__ void mma8(float* c, const uint32_t* a,
                                     uint32_t b0, uint32_t b1) {
    asm volatile("mma.sync.aligned.m16n8k8.row.col.f32.tf32.tf32.f32 "
        "{%0,%1,%2,%3}, {%4,%5,%6,%7}, {%8,%9}, {%0,%1,%2,%3};"
        : "+f"(c[0]), "+f"(c[1]), "+f"(c[2]), "+f"(c[3])
        : "r"(a[0]), "r"(a[1]), "r"(a[2]), "r"(a[3]), "r"(b0), "r"(b1));
}

// ---------------- init: out = N * b1 (un-poisons d_out) ----------------
__global__ void tnep_init_kernel(float* __restrict__ out,
                                 const float* __restrict__ b1, int n) {
    out[0] = b1[0] * (float)n;
}

__global__ __launch_bounds__(NTHR, 1)
void tnep_mma(const float* __restrict__ q,
              const float* __restrict__ W0,
              const float* __restrict__ b0,
              const float* __restrict__ W1,
              const int*   __restrict__ Z,
              float* __restrict__ out,
              int n, int per)
{
    extern __shared__ char smc[];
    uint32_t* sW  = (uint32_t*)(smc + SW_OFF);   // raw fp32 weights, swizzled
    float* sB0 = (float*)(smc + B0_OFF);
    float* sW1 = (float*)(smc + W1_OFF);
    int* sIdx = (int*)(smc + IDX_OFF);
    int* hist = (int*)(smc + HIST_OFF);
    int* bse  = (int*)(smc + BASE_OFF);
    int* off  = (int*)(smc + OFF_OFF);
    int* tZ   = (int*)(smc + TZ_OFF);
    int* tS   = (int*)(smc + TS_OFF);
    int* tL   = (int*)(smc + TL_OFF);
    int* nT   = (int*)(smc + NT_OFF);

    const uint32_t smb = smem_u32(smc);
    const int tid  = threadIdx.x;
    const int wid  = tid >> 5;
    const int lane = tid & 31;

    // ---- issue weight copies ASYNC (hidden behind the sort below) ----
    // W0: [t][k=d][n ^ 8*(d&7)] swizzle at float4 granularity -> raw 16B copies
    #pragma unroll
    for (int it = 0; it < 16; ++it) {                   // 8192 float4 / 512 thr
        const int i = tid + it * NTHR;
        const int t = i >> 10, j = i & 1023;
        const int d = j >> 4, n4 = j & 15;
        const uint32_t dst = smb + SW_OFF +
            (uint32_t)(t * 4096 + d * 64 + 4 * (n4 ^ (2 * (d & 7)))) * 4;
        cpa16(dst, (const float4*)W0 + i);
    }
    if (tid < 128) {
        cpa16(smb + B0_OFF + tid * 16, (const float4*)b0 + tid);
        cpa16(smb + W1_OFF + tid * 16, (const float4*)W1 + tid);
    }
    cpa_commit();

    for (int i = tid; i < IDX_CAP + 32; i += NTHR) sIdx[i] = 0;
    if (tid < NUM_TYPES) hist[tid] = 0;
    __syncthreads();

    // ---- local counting sort by type (overlaps weight cp.async) ----
    const int s   = blockIdx.x * per;
    const int cnt = max(0, min(n - s, per));
    const int cnt_pad = (cnt + 31) & ~31;

    for (int i = tid; i < cnt_pad; i += NTHR) {
        const bool v = (i < cnt);
        const int  z = v ? Z[s + i] : -1;
        const unsigned m = __match_any_sync(0xffffffffu, z);
        if (v && (lane == (__ffs(m) - 1)))
            atomicAdd(&hist[z], __popc(m));
    }
    __syncthreads();
    if (tid == 0) {
        int acc = 0, nt = 0;
        #pragma unroll
        for (int t = 0; t < NUM_TYPES; ++t) { bse[t] = acc; off[t] = acc; acc += hist[t]; }
        for (int t = 0; t < NUM_TYPES; ++t) {
            int c = hist[t], st = bse[t];
            while (c > 0 && nt < MAX_TILES) {
                tZ[nt] = t; tS[nt] = st; tL[nt] = min(32, c);
                st += 32; c -= 32; ++nt;
            }
        }
        nT[0] = nt;
    }
    __syncthreads();
    for (int i = tid; i < cnt_pad; i += NTHR) {
        const bool v = (i < cnt);
        const int  z = v ? Z[s + i] : -1;
        const unsigned m = __match_any_sync(0xffffffffu, z);
        const int leader = __ffs(m) - 1;
        const int rank   = __popc(m & ((1u << lane) - 1));
        int p0 = 0;
        if (v && lane == leader) p0 = atomicAdd(&off[z], __popc(m));
        p0 = __shfl_sync(0xffffffffu, p0, leader);
        if (v) sIdx[p0 + rank] = s + i;
    }

    cpa_wait0();          // weights have been flying during the sort
    __syncthreads();

    // ---- MMA mainloop: one warp per 32-atom type-pure tile ----
    const int ntiles = nT[0];
    const int g  = lane >> 2;       // 0..7
    const int t4 = lane & 3;        // 0..3
    uint32_t* wq = (uint32_t*)(smc + SQ_OFF) + wid * 1024;  // 32 rows x 32 k raw fp32
    const uint32_t wqb = smb + SQ_OFF + wid * 4096;
    const int srow = lane >> 3;     // staging row phase 0..3
    const int sc4  = lane & 7;      // staging col4 0..7
    float esum = 0.0f;

    for (int ti = wid; ti < ntiles; ti += NWARP) {
        const int z   = tZ[ti];
        const int ts  = tS[ti];
        const int len = tL[ti];

        float C[8][8];
        #pragma unroll
        for (int i = 0; i < 8; ++i)
            #pragma unroll
            for (int j = 0; j < 8; ++j) C[i][j] = 0.0f;

        const uint32_t* wz = sW + z * 4096;

        #pragma unroll
        for (int h = 0; h < 2; ++h) {            // k-halves: cols [32h, 32h+32)
            // stage half-tile A via cp.async (raw fp32, XOR-swizzled dst)
            #pragma unroll
            for (int it = 0; it < 8; ++it) {
                const int r = 4 * it + srow;
                const int row = sIdx[ts + r];
                const uint32_t dst = wqb + (uint32_t)(r * 32 + 4 * (sc4 ^ (r & 7))) * 4;
                cpa16(dst, q + (size_t)row * 64 + h * 32 + 4 * sc4);
            }
            cpa_commit();
            cpa_wait0();
            __syncwarp();

            #pragma unroll
            for (int kcl = 0; kcl < 4; ++kcl) {  // global kc = 4h+kcl
                const int kc = 4 * h + kcl;
                const int kx = 4 * g;            // A swizzle const (r&7==g for frag rows)
                const int k0 = 8 * kcl + t4, k4 = k0 + 4;

                // A fragments: raw fp32 from smem -> hi (rna tf32) + lo (residual, raw)
                uint32_t a0h[4], a0l[4], a1h[4], a1l[4];
                {
                    const float x0 = __uint_as_float(wq[(g     ) * 32 + (k0 ^ kx)]);
                    const float x1 = __uint_as_float(wq[(g +  8) * 32 + (k0 ^ kx)]);
                    const float x2 = __uint_as_float(wq[(g     ) * 32 + (k4 ^ kx)]);
                    const float x3 = __uint_as_float(wq[(g +  8) * 32 + (k4 ^ kx)]);
                    a0h[0] = f2tf(x0); a0l[0] = __float_as_uint(x0 - __uint_as_float(a0h[0]));
                    a0h[1] = f2tf(x1); a0l[1] = __float_as_uint(x1 - __uint_as_float(a0h[1]));
                    a0h[2] = f2tf(x2); a0l[2] = __float_as_uint(x2 - __uint_as_float(a0h[2]));
                    a0h[3] = f2tf(x3); a0l[3] = __float_as_uint(x3 - __uint_as_float(a0h[3]));
                }
                {
                    const float x0 = __uint_as_float(wq[(g + 16) * 32 + (k0 ^ kx)]);
                    const float x1 = __uint_as_float(wq[(g + 24) * 32 + (k0 ^ kx)]);
                    const float x2 = __uint_as_float(wq[(g + 16) * 32 + (k4 ^ kx)]);
                    const float x3 = __uint_as_float(wq[(g + 24) * 32 + (k4 ^ kx)]);
                    a1h[0] = f2tf(x0); a1l[0] = __float_as_uint(x0 - __uint_as_float(a1h[0]));
                    a1h[1] = f2tf(x1); a1l[1] = __float_as_uint(x1 - __uint_as_float(a1h[1]));
                    a1h[2] = f2tf(x2); a1l[2] = __float_as_uint(x2 - __uint_as_float(a1h[2]));
                    a1h[3] = f2tf(x3); a1l[3] = __float_as_uint(x3 - __uint_as_float(a1h[3]));
                }

                // B fragments: raw fp32 (HW tf32 truncation), swizzled conflict-free
                const int kb0 = 8 * kc + t4, kb1 = kb0 + 4;
                const uint32_t* wr0 = wz + kb0 * 64;
                const uint32_t* wr1 = wz + kb1 * 64;
                const int sx0 = 8 * (kb0 & 7);
                const int sx1 = 8 * (kb1 & 7);
                #pragma unroll
                for (int nt = 0; nt < 8; ++nt) {
                    const int nn = 8 * nt + g;
                    const uint32_t bf0 = wr0[nn ^ sx0];
                    const uint32_t bf1 = wr1[nn ^ sx1];
                    mma8(C[nt],     a0h, bf0, bf1);
                    mma8(C[nt],     a0l, bf0, bf1);
                    mma8(C[nt] + 4, a1h, bf0, bf1);
                    mma8(C[nt] + 4, a1l, bf0, bf1);
                }
            }
            __syncwarp();
        }

        // epilogue: bias + tanh + dot W1, mask padded rows
        const float* zb = sB0 + z * 64;
        const float* zw = sW1 + z * 64;
        const bool v0 = (g      < len), v1 = (g + 8  < len);
        const bool v2 = (g + 16 < len), v3 = (g + 24 < len);
        #pragma unroll
        for (int nt = 0; nt < 8; ++nt) {
            const int n0 = nt * 8 + 2 * t4, n1 = n0 + 1;
            const float bb0 = zb[n0], bb1 = zb[n1];
            const float ww0 = zw[n0], ww1 = zw[n1];
            if (v0) esum += fast_tanh(C[nt][0] + bb0) * ww0
                          + fast_tanh(C[nt][1] + bb1) * ww1;
            if (v1) esum += fast_tanh(C[nt][2] + bb0) * ww0
                          + fast_tanh(C[nt][3] + bb1) * ww1;
            if (v2) esum += fast_tanh(C[nt][4] + bb0) * ww0
                          + fast_tanh(C[nt][5] + bb1) * ww1;
            if (v3) esum += fast_tanh(C[nt][6] + bb0) * ww0
                          + fast_tanh(C[nt][7] + bb1) * ww1;
        }
    }

    // ---- reduce + one atomic per warp ----
    #pragma unroll
    for (int o = 16; o > 0; o >>= 1)
        esum += __shfl_xor_sync(0xffffffffu, esum, o);
    if (lane == 0)
        atomicAdd(out, esum);
}

extern "C" void kernel_launch(void* const* d_in, const int* in_sizes, int n_in,
                              void* d_out, int out_size) {
    // metadata order: descriptors, W0, b0, W1, b1, Z
    const float* q  = (const float*)d_in[0];
    const float* W0 = (const float*)d_in[1];
    const float* b0 = (const float*)d_in[2];
    const float* W1 = (const float*)d_in[3];
    const float* b1 = (const float*)d_in[4];
    const int*   Z  = (const int*)  d_in[5];
    float* out = (float*)d_out;

    const int n = in_sizes[5];            // N_ATOMS
    int per = (n + NBLK - 1) / NBLK;
    if (per > IDX_CAP) per = IDX_CAP;

    cudaFuncSetAttribute(tnep_mma,
                         cudaFuncAttributeMaxDynamicSharedMemorySize,
                         SMEM_BYTES);

    tnep_init_kernel<<<1, 1>>>(out, b1, n);
    tnep_mma<<<NBLK, NTHR, SMEM_BYTES>>>(q, W0, b0, W1, Z, out, n, per);
}